// round 6
// baseline (speedup 1.0000x reference)
#include <cuda_runtime.h>
#include <cstdint>
#include <cstddef>

#define K_DIM 4096
#define O_DIM 11008
#define BM 128
#define BN 128
#define BK 32
#define THREADS 128
#define NX (O_DIM / BN)      // 86
#define KT (K_DIM / BK)      // 128
#define PH 8                 // panel height (M-tiles) for L2-friendly raster

#define ROWBF 36             // floats per smem row -> conflict-free LDSM phases
#define ROWB  (ROWBF * 4)    // 144 bytes
#define A_STAGE (BM * ROWB)  // 18432
#define B_STAGE (BN * ROWB)  // 18432
#define STAGE   (A_STAGE + B_STAGE)     // 36864
#define SMEM_TOTAL (2 * STAGE)          // 73728 -> 3 CTAs/SM

// 180MB scratch: dequantized (tf32-rounded) weights, [O_DIM][K_DIM] row-major
__device__ float g_w[(size_t)O_DIM * K_DIM];

__device__ __forceinline__ float to_tf32(float f) {
    unsigned u;
    asm("cvt.rna.tf32.f32 %0, %1;" : "=r"(u) : "f"(f));
    return __uint_as_float(u);
}

__device__ __forceinline__ uint32_t smem_u32(const void* p) {
    uint32_t a;
    asm("{ .reg .u64 t; cvta.to.shared.u64 t, %1; cvt.u32.u64 %0, t; }" : "=r"(a) : "l"(p));
    return a;
}

__device__ __forceinline__ void cp16(uint32_t dst, const void* src) {
    asm volatile("cp.async.cg.shared.global [%0], [%1], 16;" :: "r"(dst), "l"(src));
}

__device__ __forceinline__ void ldsm4(unsigned& r0, unsigned& r1, unsigned& r2, unsigned& r3,
                                      uint32_t addr) {
    asm volatile("ldmatrix.sync.aligned.m8n8.x4.shared.b16 {%0,%1,%2,%3}, [%4];"
                 : "=r"(r0), "=r"(r1), "=r"(r2), "=r"(r3) : "r"(addr));
}

// ---------------- kernel 1: dequant W = tf32(cb[idx]) ----------------
__global__ void __launch_bounds__(256)
dequant_kernel(const int* __restrict__ widx, const float* __restrict__ cb)
{
    __shared__ float scb[256];
    const int tid = threadIdx.x;
    scb[tid] = to_tf32(cb[tid]);
    __syncthreads();
    const size_t i = (size_t)blockIdx.x * 256 + tid;
    int4 v = ((const int4*)widx)[i];
    ((float4*)g_w)[i] = make_float4(scb[v.x], scb[v.y], scb[v.z], scb[v.w]);
}

// ---------------- kernel 2: TF32 GEMM via ldmatrix fragments ----------------
__global__ void __launch_bounds__(THREADS, 3)
phirho_gemm_v5(const float* __restrict__ x,
               const float* __restrict__ bias,
               float*       __restrict__ out)
{
    extern __shared__ __align__(16) char smem[];
    const uint32_t sbase = smem_u32(smem);
    const int tid = threadIdx.x;

    // panel rasterization
    const int bid = blockIdx.x;
    const int per_panel = PH * NX;
    const int panel = bid / per_panel;
    const int r0 = bid - panel * per_panel;
    const int by = panel * PH + (r0 % PH);
    const int bx = r0 / PH;
    const int bm = by * BM;
    const int bn = bx * BN;

    const int w = tid >> 5, lane = tid & 31;
    const int wm = (w >> 1) * 64;
    const int wn = (w & 1) * 64;
    const int g = lane >> 2;         // 0..7 (fragment row group)
    const int t = lane & 3;          // 0..3

    float acc[4][8][4];
    #pragma unroll
    for (int i = 0; i < 4; i++)
        #pragma unroll
        for (int j = 0; j < 8; j++)
            #pragma unroll
            for (int c = 0; c < 4; c++)
                acc[i][j][c] = 0.0f;

    // ---- per-lane LDSM base addresses (stage 0); stage 1 = +STAGE (immediate) ----
    // A x4 for tile mt: matrix j covers rows wm+mt*16+(j&1)*8, 16B-col (j>>1)
    // B x4 for pair (nt,nt+1): matrix j covers rows wn+(nt+(j>>1))*8, 16B-col (j&1)
    const int lj = lane >> 3;        // matrix index 0..3
    const int lr = lane & 7;         // row within matrix
    uint32_t aBase[4], bBase[4];
    #pragma unroll
    for (int mt = 0; mt < 4; mt++)
        aBase[mt] = sbase + (wm + mt * 16 + (lj & 1) * 8 + lr) * ROWB + (lj >> 1) * 16;
    #pragma unroll
    for (int np = 0; np < 4; np++)   // nt pairs: (0,1),(2,3),(4,5),(6,7)
        bBase[np] = sbase + A_STAGE + (wn + (np * 2 + (lj >> 1)) * 8 + lr) * ROWB + (lj & 1) * 16;

    // fill mapping: 128 threads -> 16 rows x 8 float4 cols
    const int frow = tid >> 3;
    const int fc4  = tid & 7;
    const float* xg = x   + (size_t)(bm + frow) * K_DIM + fc4 * 4;
    const float* wg = g_w + (size_t)(bn + frow) * K_DIM + fc4 * 4;
    const uint32_t adst0 = sbase + frow * ROWB + fc4 * 16;
    const uint32_t bdst0 = sbase + A_STAGE + frow * ROWB + fc4 * 16;

    // prologue: tile 0 -> stage 0
    #pragma unroll
    for (int i = 0; i < 8; i++) {
        cp16(adst0 + i * 16 * ROWB, xg + (size_t)i * 16 * K_DIM);
        cp16(bdst0 + i * 16 * ROWB, wg + (size_t)i * 16 * K_DIM);
    }
    asm volatile("cp.async.commit_group;" ::: "memory");
    asm volatile("cp.async.wait_group 0;" ::: "memory");
    __syncthreads();

#define PREFETCH(NS, TI_NEXT)                                                   \
    do {                                                                        \
        if ((TI_NEXT) < KT) {                                                   \
            const int ktn = (TI_NEXT) * BK;                                     \
            _Pragma("unroll")                                                   \
            for (int i = 0; i < 8; i++) {                                       \
                cp16(adst0 + (NS) * STAGE + i * 16 * ROWB,                      \
                     xg + (size_t)i * 16 * K_DIM + ktn);                        \
                cp16(bdst0 + (NS) * STAGE + i * 16 * ROWB,                      \
                     wg + (size_t)i * 16 * K_DIM + ktn);                        \
            }                                                                   \
            asm volatile("cp.async.commit_group;" ::: "memory");                \
        }                                                                       \
    } while (0)

#define COMPUTE(S)                                                              \
    do {                                                                        \
        _Pragma("unroll")                                                       \
        for (int k8 = 0; k8 < BK / 8; k8++) {                                   \
            const int kb4 = k8 * 32;  /* kb*4 bytes */                          \
            unsigned af[4][4], bf[8][2];                                        \
            _Pragma("unroll")                                                   \
            for (int mt = 0; mt < 4; mt++)                                      \
                ldsm4(af[mt][0], af[mt][1], af[mt][2], af[mt][3],               \
                      aBase[mt] + (S) * STAGE + kb4);                           \
            _Pragma("unroll")                                                   \
            for (int np = 0; np < 4; np++)                                      \
                ldsm4(bf[np*2][0], bf[np*2][1], bf[np*2+1][0], bf[np*2+1][1],   \
                      bBase[np] + (S) * STAGE + kb4);                           \
            _Pragma("unroll")                                                   \
            for (int mt = 0; mt < 4; mt++)                                      \
                _Pragma("unroll")                                               \
                for (int nt = 0; nt < 8; nt++) {                                \
                    asm volatile(                                               \
                        "mma.sync.aligned.m16n8k8.row.col.f32.tf32.tf32.f32 "   \
                        "{%0,%1,%2,%3}, {%4,%5,%6,%7}, {%8,%9}, {%0,%1,%2,%3};\n" \
                        : "+f"(acc[mt][nt][0]), "+f"(acc[mt][nt][1]),           \
                          "+f"(acc[mt][nt][2]), "+f"(acc[mt][nt][3])            \
                        : "r"(af[mt][0]), "r"(af[mt][1]),                       \
                          "r"(af[mt][2]), "r"(af[mt][3]),                       \
                          "r"(bf[nt][0]), "r"(bf[nt][1]));                      \
                }                                                               \
        }                                                                       \
    } while (0)

    for (int ti = 0; ti < KT; ti += 2) {
        // stage 0 compute, prefetch ti+1 -> stage 1
        PREFETCH(1, ti + 1);
        COMPUTE(0);
        asm volatile("cp.async.wait_group 0;" ::: "memory");
        __syncthreads();
        // stage 1 compute, prefetch ti+2 -> stage 0
        PREFETCH(0, ti + 2);
        COMPUTE(1);
        asm volatile("cp.async.wait_group 0;" ::: "memory");
        __syncthreads();
    }

    // epilogue: bias add + fp32 store (all tiles full)
    #pragma unroll
    for (int nt = 0; nt < 8; nt++) {
        const int col = bn + wn + nt * 8 + t * 2;
        const float b0 = bias[col];
        const float b1 = bias[col + 1];
        #pragma unroll
        for (int mt = 0; mt < 4; mt++) {
            const int row = bm + wm + mt * 16 + g;
            float2 v0 = make_float2(acc[mt][nt][0] + b0, acc[mt][nt][1] + b1);
            float2 v1 = make_float2(acc[mt][nt][2] + b0, acc[mt][nt][3] + b1);
            *(float2*)(out + (size_t)row       * O_DIM + col) = v0;
            *(float2*)(out + (size_t)(row + 8) * O_DIM + col) = v1;
        }
    }
}

extern "C" void kernel_launch(void* const* d_in, const int* in_sizes, int n_in,
                              void* d_out, int out_size) {
    const float* x    = (const float*)d_in[0];
    const int*   widx = (const int*)  d_in[1];
    const float* cb   = (const float*)d_in[2];
    const float* bias = (const float*)d_in[3];
    float* out = (float*)d_out;

    const int ntok = in_sizes[0] / K_DIM;   // 8192
    const int ny = ntok / BM;               // 64

    static bool attr_set = false;
    if (!attr_set) {
        cudaFuncSetAttribute(phirho_gemm_v5,
                             cudaFuncAttributeMaxDynamicSharedMemorySize, SMEM_TOTAL);
        attr_set = true;
    }

    const int nvec4 = (O_DIM * K_DIM) / 4;
    dequant_kernel<<<nvec4 / 256, 256>>>(widx, cb);

    dim3 grid(NX * ny);                     // 5504
    phirho_gemm_v5<<<grid, THREADS, SMEM_TOTAL>>>(x, bias, out);
}

// round 7
// speedup vs baseline: 1.5968x; 1.5968x over previous
#include <cuda_runtime.h>
#include <cstdint>
#include <cstddef>

#define K_DIM 4096
#define O_DIM 11008
#define M_DIM 8192
#define BM 128
#define BN 128
#define THREADS 128
#define NX (O_DIM / BN)      // 86
#define K8 (K_DIM / 8)       // 512 k8-steps
#define PH 8                 // panel height for L2-friendly raster

// fragment-permuted scratch:
// chunk(m16, k8) = 512B: lane l (g=l>>2,t=l&3) holds {A[g][t],A[g+8][t],A[g][t+4],A[g+8][t+4]}
__device__ __align__(16) float g_xp[(size_t)M_DIM * K_DIM];
// chunk(n16, k8) = 512B: lane l holds {W[g][t],W[g][t+4],W[g+8][t],W[g+8][t+4]}
__device__ __align__(16) float g_wp[(size_t)O_DIM * K_DIM];

__device__ __forceinline__ float to_tf32(float f) {
    unsigned u;
    asm("cvt.rna.tf32.f32 %0, %1;" : "=r"(u) : "f"(f));
    return __uint_as_float(u);
}

// ---------- pre-pass 1: permute x into fragment order (RNA tf32 rounding) ----------
__global__ void __launch_bounds__(256)
permute_x(const float* __restrict__ x)
{
    __shared__ float sX[64][68];
    const int tid = threadIdx.x;
    const int bk = blockIdx.x;       // 64-col K block
    const int bm = blockIdx.y;       // 64-row M block

    const int row0 = tid >> 4, c4 = tid & 15;
    #pragma unroll
    for (int i = 0; i < 4; i++) {
        const int r = row0 + i * 16;
        float4 v = *(const float4*)(x + (size_t)(bm * 64 + r) * K_DIM + bk * 64 + c4 * 4);
        float4 o = make_float4(to_tf32(v.x), to_tf32(v.y), to_tf32(v.z), to_tf32(v.w));
        *(float4*)(&sX[r][c4 * 4]) = o;
    }
    __syncthreads();

    #pragma unroll
    for (int s = 0; s < 4; s++) {
        const int gs = s * 256 + tid;
        const int chunk = gs >> 5, lane = gs & 31;
        const int k8l = chunk & 7, m16l = chunk >> 3;
        const int g = lane >> 2, t = lane & 3;
        float4 o;
        o.x = sX[m16l * 16 + g    ][k8l * 8 + t    ];
        o.y = sX[m16l * 16 + 8 + g][k8l * 8 + t    ];
        o.z = sX[m16l * 16 + g    ][k8l * 8 + t + 4];
        o.w = sX[m16l * 16 + 8 + g][k8l * 8 + t + 4];
        const size_t m16g = (size_t)bm * 4 + m16l;
        const size_t k8g  = (size_t)bk * 8 + k8l;
        ((float4*)g_xp)[(m16g * K8 + k8g) * 32 + lane] = o;
    }
}

// ---------- pre-pass 2: dequant + permute W into fragment order ----------
__global__ void __launch_bounds__(256)
permute_w(const int* __restrict__ widx, const float* __restrict__ cb)
{
    __shared__ float sW[64][68];
    __shared__ float scb[256];
    const int tid = threadIdx.x;
    scb[tid] = to_tf32(cb[tid]);
    __syncthreads();

    const int bk = blockIdx.x;       // 64-col K block
    const int bo = blockIdx.y;       // 64-row O block

    const int row0 = tid >> 4, c4 = tid & 15;
    #pragma unroll
    for (int i = 0; i < 4; i++) {
        const int r = row0 + i * 16;
        int4 v = *(const int4*)(widx + (size_t)(bo * 64 + r) * K_DIM + bk * 64 + c4 * 4);
        float4 o = make_float4(scb[v.x], scb[v.y], scb[v.z], scb[v.w]);
        *(float4*)(&sW[r][c4 * 4]) = o;
    }
    __syncthreads();

    #pragma unroll
    for (int s = 0; s < 4; s++) {
        const int gs = s * 256 + tid;
        const int chunk = gs >> 5, lane = gs & 31;
        const int k8l = chunk & 7, n16l = chunk >> 3;
        const int g = lane >> 2, t = lane & 3;
        float4 o;
        o.x = sW[n16l * 16 + g    ][k8l * 8 + t    ];
        o.y = sW[n16l * 16 + g    ][k8l * 8 + t + 4];
        o.z = sW[n16l * 16 + 8 + g][k8l * 8 + t    ];
        o.w = sW[n16l * 16 + 8 + g][k8l * 8 + t + 4];
        const size_t n16g = (size_t)bo * 4 + n16l;
        const size_t k8g  = (size_t)bk * 8 + k8l;
        ((float4*)g_wp)[(n16g * K8 + k8g) * 32 + lane] = o;
    }
}

// ---------- GEMM: no smem, no barriers; fragments direct from L1/L2 ----------
__global__ void __launch_bounds__(THREADS, 2)
phirho_gemm_v6(const float* __restrict__ bias, float* __restrict__ out)
{
    const int tid = threadIdx.x;

    // panel rasterization
    const int bid = blockIdx.x;
    const int per_panel = PH * NX;
    const int panel = bid / per_panel;
    const int r0 = bid - panel * per_panel;
    const int by = panel * PH + (r0 % PH);
    const int bx = r0 / PH;
    const int bm = by * BM;
    const int bn = bx * BN;

    const int w = tid >> 5, lane = tid & 31;
    const int wm = (w >> 1) * 64;
    const int wn = (w & 1) * 64;
    const int g = lane >> 2, t = lane & 3;

    const float4* __restrict__ A4 = (const float4*)g_xp;
    const float4* __restrict__ B4 = (const float4*)g_wp;
    const size_t aBase = ((size_t)((bm + wm) >> 4) * K8) * 32 + lane;
    const size_t bBase = ((size_t)((bn + wn) >> 4) * K8) * 32 + lane;
    const size_t MT = (size_t)K8 * 32;   // chunk stride per 16 rows

    float acc[4][8][4];
    #pragma unroll
    for (int i = 0; i < 4; i++)
        #pragma unroll
        for (int j = 0; j < 8; j++)
            #pragma unroll
            for (int c = 0; c < 4; c++)
                acc[i][j][c] = 0.0f;

    float4 ab[2][4], bb[2][4];

#define LOADK(BUF, KK)                                                \
    do {                                                              \
        _Pragma("unroll")                                             \
        for (int mt = 0; mt < 4; mt++)                                \
            ab[BUF][mt] = A4[aBase + (size_t)mt * MT + (size_t)(KK) * 32]; \
        _Pragma("unroll")                                             \
        for (int np = 0; np < 4; np++)                                \
            bb[BUF][np] = B4[bBase + (size_t)np * MT + (size_t)(KK) * 32]; \
    } while (0)

    LOADK(0, 0);

    #pragma unroll 2
    for (int k8 = 0; k8 < K8; k8++) {
        const int cur = k8 & 1;
        if (k8 + 1 < K8) LOADK(cur ^ 1, k8 + 1);

        #pragma unroll
        for (int mt = 0; mt < 4; mt++) {
            const unsigned a0 = __float_as_uint(ab[cur][mt].x);
            const unsigned a1 = __float_as_uint(ab[cur][mt].y);
            const unsigned a2 = __float_as_uint(ab[cur][mt].z);
            const unsigned a3 = __float_as_uint(ab[cur][mt].w);
            #pragma unroll
            for (int nt = 0; nt < 8; nt++) {
                const int np = nt >> 1;
                const unsigned b0 = (nt & 1) ? __float_as_uint(bb[cur][np].z)
                                             : __float_as_uint(bb[cur][np].x);
                const unsigned b1 = (nt & 1) ? __float_as_uint(bb[cur][np].w)
                                             : __float_as_uint(bb[cur][np].y);
                asm volatile(
                    "mma.sync.aligned.m16n8k8.row.col.f32.tf32.tf32.f32 "
                    "{%0,%1,%2,%3}, {%4,%5,%6,%7}, {%8,%9}, {%0,%1,%2,%3};\n"
                    : "+f"(acc[mt][nt][0]), "+f"(acc[mt][nt][1]),
                      "+f"(acc[mt][nt][2]), "+f"(acc[mt][nt][3])
                    : "r"(a0), "r"(a1), "r"(a2), "r"(a3), "r"(b0), "r"(b1));
            }
        }
        if ((k8 & 63) == 63) __syncthreads();   // re-converge warps for L1 reuse
    }

    // epilogue: bias add + fp32 store (all tiles full)
    #pragma unroll
    for (int nt = 0; nt < 8; nt++) {
        const int col = bn + wn + nt * 8 + t * 2;
        const float b0 = bias[col];
        const float b1 = bias[col + 1];
        #pragma unroll
        for (int mt = 0; mt < 4; mt++) {
            const int row = bm + wm + mt * 16 + g;
            float2 v0 = make_float2(acc[mt][nt][0] + b0, acc[mt][nt][1] + b1);
            float2 v1 = make_float2(acc[mt][nt][2] + b0, acc[mt][nt][3] + b1);
            *(float2*)(out + (size_t)row       * O_DIM + col) = v0;
            *(float2*)(out + (size_t)(row + 8) * O_DIM + col) = v1;
        }
    }
}

extern "C" void kernel_launch(void* const* d_in, const int* in_sizes, int n_in,
                              void* d_out, int out_size) {
    const float* x    = (const float*)d_in[0];
    const int*   widx = (const int*)  d_in[1];
    const float* cb   = (const float*)d_in[2];
    const float* bias = (const float*)d_in[3];
    float* out = (float*)d_out;

    const int ntok = in_sizes[0] / K_DIM;   // 8192
    const int ny = ntok / BM;               // 64

    // pre-pass: permute x and dequant+permute W into fragment layouts
    permute_x<<<dim3(K_DIM / 64, ntok / 64), 256>>>(x);
    permute_w<<<dim3(K_DIM / 64, O_DIM / 64), 256>>>(widx, cb);

    // GEMM
    dim3 grid(NX * ny);                     // 5504
    phirho_gemm_v6<<<grid, THREADS>>>(bias, out);
}

// round 8
// speedup vs baseline: 1.6236x; 1.0168x over previous
#include <cuda_runtime.h>
#include <cstdint>
#include <cstddef>

#define K_DIM 4096
#define O_DIM 11008
#define M_DIM 8192
#define BM 128
#define BN 128
#define THREADS 128
#define NX (O_DIM / BN)      // 86
#define K8 (K_DIM / 8)       // 512 k8-steps
#define PH 8                 // panel height for L2-friendly raster

// fragment-permuted scratch:
// chunk(m16, k8) = 512B: lane l (g=l>>2,t=l&3) holds {A[g][t],A[g+8][t],A[g][t+4],A[g+8][t+4]}
__device__ __align__(16) float g_xp[(size_t)M_DIM * K_DIM];
// chunk(n16, k8) = 512B: lane l holds {W[g][t],W[g][t+4],W[g+8][t],W[g+8][t+4]}
__device__ __align__(16) float g_wp[(size_t)O_DIM * K_DIM];

__device__ __forceinline__ float to_tf32(float f) {
    unsigned u;
    asm("cvt.rna.tf32.f32 %0, %1;" : "=r"(u) : "f"(f));
    return __uint_as_float(u);
}

// ---------- pre-pass 1: permute x into fragment order (RNA tf32 rounding) ----------
__global__ void __launch_bounds__(256)
permute_x(const float* __restrict__ x)
{
    __shared__ float sX[64][68];
    const int tid = threadIdx.x;
    const int bk = blockIdx.x;       // 64-col K block
    const int bm = blockIdx.y;       // 64-row M block

    const int row0 = tid >> 4, c4 = tid & 15;
    #pragma unroll
    for (int i = 0; i < 4; i++) {
        const int r = row0 + i * 16;
        float4 v = *(const float4*)(x + (size_t)(bm * 64 + r) * K_DIM + bk * 64 + c4 * 4);
        float4 o = make_float4(to_tf32(v.x), to_tf32(v.y), to_tf32(v.z), to_tf32(v.w));
        *(float4*)(&sX[r][c4 * 4]) = o;
    }
    __syncthreads();

    #pragma unroll
    for (int s = 0; s < 4; s++) {
        const int gs = s * 256 + tid;
        const int chunk = gs >> 5, lane = gs & 31;
        const int k8l = chunk & 7, m16l = chunk >> 3;
        const int g = lane >> 2, t = lane & 3;
        float4 o;
        o.x = sX[m16l * 16 + g    ][k8l * 8 + t    ];
        o.y = sX[m16l * 16 + 8 + g][k8l * 8 + t    ];
        o.z = sX[m16l * 16 + g    ][k8l * 8 + t + 4];
        o.w = sX[m16l * 16 + 8 + g][k8l * 8 + t + 4];
        const size_t m16g = (size_t)bm * 4 + m16l;
        const size_t k8g  = (size_t)bk * 8 + k8l;
        ((float4*)g_xp)[(m16g * K8 + k8g) * 32 + lane] = o;
    }
}

// ---------- pre-pass 2: dequant + permute W into fragment order ----------
__global__ void __launch_bounds__(256)
permute_w(const int* __restrict__ widx, const float* __restrict__ cb)
{
    __shared__ float sW[64][68];
    __shared__ float scb[256];
    const int tid = threadIdx.x;
    scb[tid] = to_tf32(cb[tid]);
    __syncthreads();

    const int bk = blockIdx.x;       // 64-col K block
    const int bo = blockIdx.y;       // 64-row O block

    const int row0 = tid >> 4, c4 = tid & 15;
    #pragma unroll
    for (int i = 0; i < 4; i++) {
        const int r = row0 + i * 16;
        int4 v = *(const int4*)(widx + (size_t)(bo * 64 + r) * K_DIM + bk * 64 + c4 * 4);
        float4 o = make_float4(scb[v.x], scb[v.y], scb[v.z], scb[v.w]);
        *(float4*)(&sW[r][c4 * 4]) = o;
    }
    __syncthreads();

    #pragma unroll
    for (int s = 0; s < 4; s++) {
        const int gs = s * 256 + tid;
        const int chunk = gs >> 5, lane = gs & 31;
        const int k8l = chunk & 7, n16l = chunk >> 3;
        const int g = lane >> 2, t = lane & 3;
        float4 o;
        o.x = sW[n16l * 16 + g    ][k8l * 8 + t    ];
        o.y = sW[n16l * 16 + g    ][k8l * 8 + t + 4];
        o.z = sW[n16l * 16 + 8 + g][k8l * 8 + t    ];
        o.w = sW[n16l * 16 + 8 + g][k8l * 8 + t + 4];
        const size_t n16g = (size_t)bo * 4 + n16l;
        const size_t k8g  = (size_t)bk * 8 + k8l;
        ((float4*)g_wp)[(n16g * K8 + k8g) * 32 + lane] = o;
    }
}

// ---------- GEMM: no smem; fragments via L1 with distance-2 software prefetch ----------
__global__ void __launch_bounds__(THREADS, 2)
phirho_gemm_v7(const float* __restrict__ bias, float* __restrict__ out)
{
    const int tid = threadIdx.x;

    // panel rasterization
    const int bid = blockIdx.x;
    const int per_panel = PH * NX;
    const int panel = bid / per_panel;
    const int r0 = bid - panel * per_panel;
    const int by = panel * PH + (r0 % PH);
    const int bx = r0 / PH;
    const int bm = by * BM;
    const int bn = bx * BN;

    const int w = tid >> 5, lane = tid & 31;
    const int wm = (w >> 1) * 64;
    const int wn = (w & 1) * 64;
    const int g = lane >> 2, t = lane & 3;

    const float4* __restrict__ A4 = (const float4*)g_xp;
    const float4* __restrict__ B4 = (const float4*)g_wp;
    const size_t aBase = ((size_t)((bm + wm) >> 4) * K8) * 32 + lane;
    const size_t bBase = ((size_t)((bn + wn) >> 4) * K8) * 32 + lane;
    const size_t MT = (size_t)K8 * 32;   // chunk stride per 16 rows

    float acc[4][8][4];
    #pragma unroll
    for (int i = 0; i < 4; i++)
        #pragma unroll
        for (int j = 0; j < 8; j++)
            #pragma unroll
            for (int c = 0; c < 4; c++)
                acc[i][j][c] = 0.0f;

    float4 ab[2][4], bb[2][4];

#define LOADK(BUF, KK)                                                \
    do {                                                              \
        _Pragma("unroll")                                             \
        for (int mt = 0; mt < 4; mt++)                                \
            ab[BUF][mt] = A4[aBase + (size_t)mt * MT + (size_t)(KK) * 32]; \
        _Pragma("unroll")                                             \
        for (int np = 0; np < 4; np++)                                \
            bb[BUF][np] = B4[bBase + (size_t)np * MT + (size_t)(KK) * 32]; \
    } while (0)

// distance-2 L1 prefetch: no register writeback, no scoreboard
#define PREFK(KK)                                                              \
    do {                                                                       \
        _Pragma("unroll")                                                      \
        for (int mt = 0; mt < 4; mt++)                                         \
            asm volatile("prefetch.global.L1 [%0];"                            \
                :: "l"(A4 + aBase + (size_t)mt * MT + (size_t)(KK) * 32));     \
        _Pragma("unroll")                                                      \
        for (int np = 0; np < 4; np++)                                         \
            asm volatile("prefetch.global.L1 [%0];"                            \
                :: "l"(B4 + bBase + (size_t)np * MT + (size_t)(KK) * 32));     \
    } while (0)

    LOADK(0, 0);
    PREFK(1);

    #pragma unroll 4
    for (int k8 = 0; k8 < K8; k8++) {
        const int cur = k8 & 1;
        if (k8 + 1 < K8) LOADK(cur ^ 1, k8 + 1);
        if (k8 + 2 < K8) PREFK(k8 + 2);

        #pragma unroll
        for (int mt = 0; mt < 4; mt++) {
            const unsigned a0 = __float_as_uint(ab[cur][mt].x);
            const unsigned a1 = __float_as_uint(ab[cur][mt].y);
            const unsigned a2 = __float_as_uint(ab[cur][mt].z);
            const unsigned a3 = __float_as_uint(ab[cur][mt].w);
            #pragma unroll
            for (int nt = 0; nt < 8; nt++) {
                const int np = nt >> 1;
                const unsigned b0 = (nt & 1) ? __float_as_uint(bb[cur][np].z)
                                             : __float_as_uint(bb[cur][np].x);
                const unsigned b1 = (nt & 1) ? __float_as_uint(bb[cur][np].w)
                                             : __float_as_uint(bb[cur][np].y);
                asm volatile(
                    "mma.sync.aligned.m16n8k8.row.col.f32.tf32.tf32.f32 "
                    "{%0,%1,%2,%3}, {%4,%5,%6,%7}, {%8,%9}, {%0,%1,%2,%3};\n"
                    : "+f"(acc[mt][nt][0]), "+f"(acc[mt][nt][1]),
                      "+f"(acc[mt][nt][2]), "+f"(acc[mt][nt][3])
                    : "r"(a0), "r"(a1), "r"(a2), "r"(a3), "r"(b0), "r"(b1));
            }
        }
        if ((k8 & 63) == 63) __syncthreads();   // re-converge warps for L1 reuse
    }

    // epilogue: bias add + fp32 store (all tiles full)
    #pragma unroll
    for (int nt = 0; nt < 8; nt++) {
        const int col = bn + wn + nt * 8 + t * 2;
        const float b0 = bias[col];
        const float b1 = bias[col + 1];
        #pragma unroll
        for (int mt = 0; mt < 4; mt++) {
            const int row = bm + wm + mt * 16 + g;
            float2 v0 = make_float2(acc[mt][nt][0] + b0, acc[mt][nt][1] + b1);
            float2 v1 = make_float2(acc[mt][nt][2] + b0, acc[mt][nt][3] + b1);
            *(float2*)(out + (size_t)row       * O_DIM + col) = v0;
            *(float2*)(out + (size_t)(row + 8) * O_DIM + col) = v1;
        }
    }
}

extern "C" void kernel_launch(void* const* d_in, const int* in_sizes, int n_in,
                              void* d_out, int out_size) {
    const float* x    = (const float*)d_in[0];
    const int*   widx = (const int*)  d_in[1];
    const float* cb   = (const float*)d_in[2];
    const float* bias = (const float*)d_in[3];
    float* out = (float*)d_out;

    const int ntok = in_sizes[0] / K_DIM;   // 8192
    const int ny = ntok / BM;               // 64

    // pre-pass: permute x and dequant+permute W into fragment layouts
    permute_x<<<dim3(K_DIM / 64, ntok / 64), 256>>>(x);
    permute_w<<<dim3(K_DIM / 64, O_DIM / 64), 256>>>(widx, cb);

    // GEMM
    dim3 grid(NX * ny);                     // 5504
    phirho_gemm_v7<<<grid, THREADS>>>(bias, out);
}